// round 1
// baseline (speedup 1.0000x reference)
#include <cuda_runtime.h>
#include <cstdint>
#include <cstddef>

#define S_LEN 2048
#define HID   1024
#define NH    16
#define HD    64
#define BATCH 2
#define M_TOT (BATCH * S_LEN)   // 4096

// ---------------- scratch (static device arrays; no allocation) -------------
__device__ float g_Q[(size_t)M_TOT * HID];
__device__ float g_K[(size_t)M_TOT * HID];
__device__ float g_V[(size_t)M_TOT * HID];

// ---------------- helpers ---------------------------------------------------
__device__ __forceinline__ uint32_t f2tf32(float x) {
    uint32_t u;
    asm("cvt.rna.tf32.f32 %0, %1;" : "=r"(u) : "f"(x));
    return u;
}
__device__ __forceinline__ float tf32f(float x) { return __uint_as_float(f2tf32(x)); }

// D += A * B  (m16n8k8, row.col, tf32 in, fp32 accum)
__device__ __forceinline__ void mma_tf32(float d[4], const uint32_t a[4], const uint32_t b[2]) {
    asm volatile(
        "mma.sync.aligned.m16n8k8.row.col.f32.tf32.tf32.f32 "
        "{%0,%1,%2,%3}, {%4,%5,%6,%7}, {%8,%9}, {%0,%1,%2,%3};\n"
        : "+f"(d[0]), "+f"(d[1]), "+f"(d[2]), "+f"(d[3])
        : "r"(a[0]), "r"(a[1]), "r"(a[2]), "r"(a[3]), "r"(b[0]), "r"(b[1]));
}

// ============================================================================
// Kernel 1: QKV projection.  Y = X @ W^T + b   (X: [4096,1024], W: [1024,1024])
// CTA tile 128x128, BK=32, 8 warps as 4(m) x 2(n), warp tile 32x64.
// blockIdx.z selects which of Q/K/V.
// ============================================================================
__global__ __launch_bounds__(256, 1) void qkv_kernel(
    const float* __restrict__ X,
    const float* __restrict__ Wq, const float* __restrict__ bq,
    const float* __restrict__ Wk, const float* __restrict__ bk,
    const float* __restrict__ Wv, const float* __restrict__ bv)
{
    const float* W; const float* bias; float* Y;
    if (blockIdx.z == 0)      { W = Wq; bias = bq; Y = g_Q; }
    else if (blockIdx.z == 1) { W = Wk; bias = bk; Y = g_K; }
    else                      { W = Wv; bias = bv; Y = g_V; }

    __shared__ float sA[128][36];   // X tile   [m][k]
    __shared__ float sB[128][36];   // W tile   [n][k]

    const int tid = threadIdx.x, wid = tid >> 5, lane = tid & 31;
    const int g = lane >> 2, tig = lane & 3;
    const int wm = wid & 3, wn = wid >> 2;
    const int m0 = blockIdx.y * 128, n0 = blockIdx.x * 128;

    float acc[2][8][4];
#pragma unroll
    for (int i = 0; i < 2; i++)
#pragma unroll
        for (int j = 0; j < 8; j++)
#pragma unroll
            for (int k = 0; k < 4; k++) acc[i][j][k] = 0.f;

    for (int kt = 0; kt < HID; kt += 32) {
        __syncthreads();
#pragma unroll
        for (int i = 0; i < 4; i++) {
            int idx = tid + i * 256;          // 1024 float4 total
            int r = idx >> 3;
            int c = (idx & 7) * 4;
            float4 a = *reinterpret_cast<const float4*>(X + (size_t)(m0 + r) * HID + kt + c);
            float4 ta = make_float4(tf32f(a.x), tf32f(a.y), tf32f(a.z), tf32f(a.w));
            *reinterpret_cast<float4*>(&sA[r][c]) = ta;
            float4 w = *reinterpret_cast<const float4*>(W + (size_t)(n0 + r) * HID + kt + c);
            float4 tw = make_float4(tf32f(w.x), tf32f(w.y), tf32f(w.z), tf32f(w.w));
            *reinterpret_cast<float4*>(&sB[r][c]) = tw;
        }
        __syncthreads();
#pragma unroll
        for (int ks = 0; ks < 4; ks++) {
            const int kb = ks * 8;
            uint32_t af[2][4];
#pragma unroll
            for (int mt = 0; mt < 2; mt++) {
                const int r = wm * 32 + mt * 16;
                af[mt][0] = __float_as_uint(sA[r + g    ][kb + tig    ]);
                af[mt][1] = __float_as_uint(sA[r + g + 8][kb + tig    ]);
                af[mt][2] = __float_as_uint(sA[r + g    ][kb + tig + 4]);
                af[mt][3] = __float_as_uint(sA[r + g + 8][kb + tig + 4]);
            }
#pragma unroll
            for (int nt = 0; nt < 8; nt++) {
                const int n = wn * 64 + nt * 8 + g;
                uint32_t bf[2];
                bf[0] = __float_as_uint(sB[n][kb + tig    ]);
                bf[1] = __float_as_uint(sB[n][kb + tig + 4]);
                mma_tf32(acc[0][nt], af[0], bf);
                mma_tf32(acc[1][nt], af[1], bf);
            }
        }
    }

    // epilogue: bias add, float2 stores
#pragma unroll
    for (int mt = 0; mt < 2; mt++) {
        const int r = m0 + wm * 32 + mt * 16 + g;
#pragma unroll
        for (int nt = 0; nt < 8; nt++) {
            const int c = n0 + wn * 64 + nt * 8 + 2 * tig;
            const float b0 = bias[c], b1 = bias[c + 1];
            *reinterpret_cast<float2*>(Y + (size_t)r * HID + c) =
                make_float2(acc[mt][nt][0] + b0, acc[mt][nt][1] + b1);
            *reinterpret_cast<float2*>(Y + (size_t)(r + 8) * HID + c) =
                make_float2(acc[mt][nt][2] + b0, acc[mt][nt][3] + b1);
        }
    }
}

// ============================================================================
// Kernel 2: attention. One CTA per (b, h, 128-row q tile).
// Sweep 1: rowsum(exp(QK^T/8)) over all K tiles (scores recomputed, not stored).
// Sweep 2: probs = exp(s)/L written to gmem; ctx += P @ V (tf32 MMA via SMEM P).
// ============================================================================
#define SQ_STRIDE 72
#define SP_STRIDE 132
#define ATTN_SMEM_BYTES ((3 * 128 * SQ_STRIDE + 128 * SP_STRIDE + 256) * 4)

__device__ __forceinline__ void compute_scores(
    const float (*sQ)[SQ_STRIDE], const float (*sK)[SQ_STRIDE],
    int wm, int wn, int g, int tig, float accS[2][8][4])
{
#pragma unroll
    for (int i = 0; i < 2; i++)
#pragma unroll
        for (int j = 0; j < 8; j++)
#pragma unroll
            for (int k = 0; k < 4; k++) accS[i][j][k] = 0.f;
#pragma unroll
    for (int ks = 0; ks < 8; ks++) {
        const int kb = ks * 8;
        uint32_t af[2][4];
#pragma unroll
        for (int mt = 0; mt < 2; mt++) {
            const int r = wm * 32 + mt * 16;
            af[mt][0] = __float_as_uint(sQ[r + g    ][kb + tig    ]);
            af[mt][1] = __float_as_uint(sQ[r + g + 8][kb + tig    ]);
            af[mt][2] = __float_as_uint(sQ[r + g    ][kb + tig + 4]);
            af[mt][3] = __float_as_uint(sQ[r + g + 8][kb + tig + 4]);
        }
#pragma unroll
        for (int nt = 0; nt < 8; nt++) {
            const int n = wn * 64 + nt * 8 + g;
            uint32_t bf[2];
            bf[0] = __float_as_uint(sK[n][kb + tig    ]);
            bf[1] = __float_as_uint(sK[n][kb + tig + 4]);
            mma_tf32(accS[0][nt], af[0], bf);
            mma_tf32(accS[1][nt], af[1], bf);
        }
    }
}

__global__ __launch_bounds__(256, 1) void attn_kernel(
    float* __restrict__ ctx_out, float* __restrict__ probs_out)
{
    extern __shared__ float sm[];
    float (*sQ)[SQ_STRIDE] = reinterpret_cast<float (*)[SQ_STRIDE]>(sm);
    float (*sK)[SQ_STRIDE] = reinterpret_cast<float (*)[SQ_STRIDE]>(sm + 128 * SQ_STRIDE);
    float (*sV)[SQ_STRIDE] = reinterpret_cast<float (*)[SQ_STRIDE]>(sm + 2 * 128 * SQ_STRIDE);
    float (*sP)[SP_STRIDE] = reinterpret_cast<float (*)[SP_STRIDE]>(sm + 3 * 128 * SQ_STRIDE);
    float* sL = sm + 3 * 128 * SQ_STRIDE + 128 * SP_STRIDE;
    float* sR = sL + 128;

    const int tid = threadIdx.x, wid = tid >> 5, lane = tid & 31;
    const int g = lane >> 2, tig = lane & 3;
    const int wm = wid & 3, wn = wid >> 2;

    const int q0 = blockIdx.x * 128;
    const int h  = blockIdx.y;
    const int b  = blockIdx.z;

    const float* Qg = g_Q + (size_t)b * S_LEN * HID + (size_t)h * HD;
    const float* Kg = g_K + (size_t)b * S_LEN * HID + (size_t)h * HD;
    const float* Vg = g_V + (size_t)b * S_LEN * HID + (size_t)h * HD;

    // load Q tile (128 x 64), convert to tf32
#pragma unroll
    for (int i = 0; i < 8; i++) {
        int idx = tid + i * 256;              // 2048 float4
        int r = idx >> 4, c = (idx & 15) * 4;
        float4 v = *reinterpret_cast<const float4*>(Qg + (size_t)(q0 + r) * HID + c);
        *reinterpret_cast<float4*>(&sQ[r][c]) =
            make_float4(tf32f(v.x), tf32f(v.y), tf32f(v.z), tf32f(v.w));
    }
    if (tid < 128) sL[tid] = 0.f;
    __syncthreads();

    // -------- sweep 1: row sums of exp(scores) --------
    for (int kt = 0; kt < 16; kt++) {
        const int k0 = kt * 128;
        if (kt) __syncthreads();
#pragma unroll
        for (int i = 0; i < 8; i++) {
            int idx = tid + i * 256;
            int r = idx >> 4, c = (idx & 15) * 4;
            float4 v = *reinterpret_cast<const float4*>(Kg + (size_t)(k0 + r) * HID + c);
            *reinterpret_cast<float4*>(&sK[r][c]) =
                make_float4(tf32f(v.x), tf32f(v.y), tf32f(v.z), tf32f(v.w));
        }
        __syncthreads();

        float accS[2][8][4];
        compute_scores(sQ, sK, wm, wn, g, tig, accS);

        float ls[4] = {0.f, 0.f, 0.f, 0.f};
#pragma unroll
        for (int mt = 0; mt < 2; mt++)
#pragma unroll
            for (int nt = 0; nt < 8; nt++) {
                ls[2 * mt]     += __expf(accS[mt][nt][0] * 0.125f) + __expf(accS[mt][nt][1] * 0.125f);
                ls[2 * mt + 1] += __expf(accS[mt][nt][2] * 0.125f) + __expf(accS[mt][nt][3] * 0.125f);
            }
#pragma unroll
        for (int o = 1; o < 4; o <<= 1)
#pragma unroll
            for (int j = 0; j < 4; j++) ls[j] += __shfl_xor_sync(0xffffffffu, ls[j], o);
        if (tig == 0) {
            atomicAdd(&sL[wm * 32      + g], ls[0]);
            atomicAdd(&sL[wm * 32 + 8  + g], ls[1]);
            atomicAdd(&sL[wm * 32 + 16 + g], ls[2]);
            atomicAdd(&sL[wm * 32 + 24 + g], ls[3]);
        }
    }
    __syncthreads();
    if (tid < 128) sR[tid] = 1.0f / sL[tid];

    float accO[8][4];
#pragma unroll
    for (int j = 0; j < 8; j++)
#pragma unroll
        for (int k = 0; k < 4; k++) accO[j][k] = 0.f;

    const size_t prob_base = (((size_t)(b * NH + h)) * S_LEN + q0) * S_LEN;

    // -------- sweep 2: probs out + ctx accumulate --------
    for (int kt = 0; kt < 16; kt++) {
        const int k0 = kt * 128;
        __syncthreads();   // prev P@V done (and sR ready on first iter)
#pragma unroll
        for (int i = 0; i < 8; i++) {
            int idx = tid + i * 256;
            int r = idx >> 4, c = (idx & 15) * 4;
            float4 v = *reinterpret_cast<const float4*>(Kg + (size_t)(k0 + r) * HID + c);
            *reinterpret_cast<float4*>(&sK[r][c]) =
                make_float4(tf32f(v.x), tf32f(v.y), tf32f(v.z), tf32f(v.w));
            float4 u = *reinterpret_cast<const float4*>(Vg + (size_t)(k0 + r) * HID + c);
            *reinterpret_cast<float4*>(&sV[r][c]) =
                make_float4(tf32f(u.x), tf32f(u.y), tf32f(u.z), tf32f(u.w));
        }
        __syncthreads();

        float accS[2][8][4];
        compute_scores(sQ, sK, wm, wn, g, tig, accS);

        const float rv[4] = { sR[wm * 32 + g],      sR[wm * 32 + 8 + g],
                              sR[wm * 32 + 16 + g], sR[wm * 32 + 24 + g] };
#pragma unroll
        for (int mt = 0; mt < 2; mt++) {
            const int ra = wm * 32 + mt * 16 + g;
            const float rvA = rv[2 * mt], rvB = rv[2 * mt + 1];
#pragma unroll
            for (int nt = 0; nt < 8; nt++) {
                const int col = wn * 64 + nt * 8 + 2 * tig;
                float p0 = __expf(accS[mt][nt][0] * 0.125f) * rvA;
                float p1 = __expf(accS[mt][nt][1] * 0.125f) * rvA;
                float p2 = __expf(accS[mt][nt][2] * 0.125f) * rvB;
                float p3 = __expf(accS[mt][nt][3] * 0.125f) * rvB;
                sP[ra    ][col] = tf32f(p0); sP[ra    ][col + 1] = tf32f(p1);
                sP[ra + 8][col] = tf32f(p2); sP[ra + 8][col + 1] = tf32f(p3);
                *reinterpret_cast<float2*>(probs_out + prob_base + (size_t)ra * S_LEN + k0 + col) =
                    make_float2(p0, p1);
                *reinterpret_cast<float2*>(probs_out + prob_base + (size_t)(ra + 8) * S_LEN + k0 + col) =
                    make_float2(p2, p3);
            }
        }
        __syncthreads();

        // P @ V : warp 'wid' owns ctx rows [16*wid, 16*wid+16), cols 0..63
#pragma unroll
        for (int ks = 0; ks < 16; ks++) {
            const int kb = ks * 8;
            const int r = wid * 16;
            uint32_t af[4];
            af[0] = __float_as_uint(sP[r + g    ][kb + tig    ]);
            af[1] = __float_as_uint(sP[r + g + 8][kb + tig    ]);
            af[2] = __float_as_uint(sP[r + g    ][kb + tig + 4]);
            af[3] = __float_as_uint(sP[r + g + 8][kb + tig + 4]);
#pragma unroll
            for (int nt = 0; nt < 8; nt++) {
                uint32_t bf[2];
                bf[0] = __float_as_uint(sV[kb + tig    ][nt * 8 + g]);
                bf[1] = __float_as_uint(sV[kb + tig + 4][nt * 8 + g]);
                mma_tf32(accO[nt], af, bf);
            }
        }
    }

    // ctx epilogue: [B, S, NH*HD] layout
    {
        const int r = wid * 16 + g;
        float* out0 = ctx_out + ((size_t)b * S_LEN + q0 + r) * HID + h * HD;
        float* out1 = ctx_out + ((size_t)b * S_LEN + q0 + r + 8) * HID + h * HD;
#pragma unroll
        for (int nt = 0; nt < 8; nt++) {
            const int c = nt * 8 + 2 * tig;
            *reinterpret_cast<float2*>(out0 + c) = make_float2(accO[nt][0], accO[nt][1]);
            *reinterpret_cast<float2*>(out1 + c) = make_float2(accO[nt][2], accO[nt][3]);
        }
    }
}

// ============================================================================
// launch
// ============================================================================
extern "C" void kernel_launch(void* const* d_in, const int* in_sizes, int n_in,
                              void* d_out, int out_size)
{
    const float* X  = (const float*)d_in[0];
    const float* Wq = (const float*)d_in[1];
    const float* bq = (const float*)d_in[2];
    const float* Wk = (const float*)d_in[3];
    const float* bk = (const float*)d_in[4];
    const float* Wv = (const float*)d_in[5];
    const float* bv = (const float*)d_in[6];

    float* ctx   = (float*)d_out;                                  // [2,2048,1024]
    float* probs = ctx + (size_t)BATCH * S_LEN * HID;              // [2,16,2048,2048]

    qkv_kernel<<<dim3(HID / 128, M_TOT / 128, 3), 256>>>(X, Wq, bq, Wk, bk, Wv, bv);

    cudaFuncSetAttribute(attn_kernel, cudaFuncAttributeMaxDynamicSharedMemorySize,
                         ATTN_SMEM_BYTES);
    attn_kernel<<<dim3(S_LEN / 128, NH, BATCH), 256, ATTN_SMEM_BYTES>>>(ctx, probs);
}

// round 7
// speedup vs baseline: 2.1152x; 2.1152x over previous
#include <cuda_runtime.h>
#include <cuda_fp16.h>
#include <cstdint>
#include <cstddef>

#define S_LEN 2048
#define HID   1024
#define NH    16
#define HD    64
#define BATCH 2
#define M_TOT (BATCH * S_LEN)   // 4096

// ---------------- scratch (static device arrays; no allocation) -------------
__device__ __half g_Qh[(size_t)M_TOT * HID];
__device__ __half g_Kh[(size_t)M_TOT * HID];
__device__ __half g_Vt[(size_t)BATCH * NH * HD * S_LEN];  // [(b*NH+h)*HD+hd][s]

// ---------------- helpers ---------------------------------------------------
__device__ __forceinline__ void mma_f16(float d[4], const uint32_t a[4],
                                        uint32_t b0, uint32_t b1) {
    asm volatile(
        "mma.sync.aligned.m16n8k16.row.col.f32.f16.f16.f32 "
        "{%0,%1,%2,%3}, {%4,%5,%6,%7}, {%8,%9}, {%0,%1,%2,%3};\n"
        : "+f"(d[0]), "+f"(d[1]), "+f"(d[2]), "+f"(d[3])
        : "r"(a[0]), "r"(a[1]), "r"(a[2]), "r"(a[3]), "r"(b0), "r"(b1));
}
__device__ __forceinline__ uint32_t pack2(float lo, float hi) {
    __half2 h = __floats2half2_rn(lo, hi);
    return *reinterpret_cast<uint32_t*>(&h);
}
__device__ __forceinline__ uint32_t ldh2(const __half* p) {
    return *reinterpret_cast<const uint32_t*>(p);
}
__device__ __forceinline__ void cp16(uint32_t dst, const void* src) {
    asm volatile("cp.async.cg.shared.global [%0], [%1], 16;" :: "r"(dst), "l"(src));
}
__device__ __forceinline__ void cp_commit() {
    asm volatile("cp.async.commit_group;");
}

// ============================================================================
// Kernel 1: QKV projection, fp16 MMA, software-pipelined.
// Y = X @ W^T + b.  CTA tile 128x128, BK=32, 8 warps 4(m) x 2(n).
// z=0 -> g_Qh, z=1 -> g_Kh, z=2 -> g_Vt (transposed per-head [hd][s]).
// ============================================================================
__global__ __launch_bounds__(256, 1) void qkv_kernel(
    const float* __restrict__ X,
    const float* __restrict__ Wq, const float* __restrict__ bq,
    const float* __restrict__ Wk, const float* __restrict__ bk,
    const float* __restrict__ Wv, const float* __restrict__ bv)
{
    const float* W; const float* bias;
    if (blockIdx.z == 0)      { W = Wq; bias = bq; }
    else if (blockIdx.z == 1) { W = Wk; bias = bk; }
    else                      { W = Wv; bias = bv; }

    __shared__ __half sA[2][128][40];
    __shared__ __half sB[2][128][40];

    const int tid = threadIdx.x, wid = tid >> 5, lane = tid & 31;
    const int g = lane >> 2, tig = lane & 3;
    const int wm = wid & 3, wn = wid >> 2;
    const int m0 = blockIdx.y * 128, n0 = blockIdx.x * 128;

    float acc[2][8][4];
#pragma unroll
    for (int i = 0; i < 2; i++)
#pragma unroll
        for (int j = 0; j < 8; j++)
#pragma unroll
            for (int k = 0; k < 4; k++) acc[i][j][k] = 0.f;

    float4 ra[4], rb[4];
    // prologue load kt=0
#pragma unroll
    for (int i = 0; i < 4; i++) {
        int idx = tid + i * 256, r = idx >> 3, c = (idx & 7) * 4;
        ra[i] = *reinterpret_cast<const float4*>(X + (size_t)(m0 + r) * HID + c);
        rb[i] = *reinterpret_cast<const float4*>(W + (size_t)(n0 + r) * HID + c);
    }
#pragma unroll
    for (int i = 0; i < 4; i++) {
        int idx = tid + i * 256, r = idx >> 3, c = (idx & 7) * 4;
        *reinterpret_cast<__half2*>(&sA[0][r][c])     = __floats2half2_rn(ra[i].x, ra[i].y);
        *reinterpret_cast<__half2*>(&sA[0][r][c + 2]) = __floats2half2_rn(ra[i].z, ra[i].w);
        *reinterpret_cast<__half2*>(&sB[0][r][c])     = __floats2half2_rn(rb[i].x, rb[i].y);
        *reinterpret_cast<__half2*>(&sB[0][r][c + 2]) = __floats2half2_rn(rb[i].z, rb[i].w);
    }
    __syncthreads();

    for (int kt = 0; kt < 32; kt++) {
        if (kt < 31) {
#pragma unroll
            for (int i = 0; i < 4; i++) {
                int idx = tid + i * 256, r = idx >> 3, c = (idx & 7) * 4;
                ra[i] = *reinterpret_cast<const float4*>(
                    X + (size_t)(m0 + r) * HID + (kt + 1) * 32 + c);
                rb[i] = *reinterpret_cast<const float4*>(
                    W + (size_t)(n0 + r) * HID + (kt + 1) * 32 + c);
            }
        }
        const int bf = kt & 1;
#pragma unroll
        for (int ks = 0; ks < 2; ks++) {
            const int kb = ks * 16;
            uint32_t af[2][4];
#pragma unroll
            for (int mt = 0; mt < 2; mt++) {
                const int r = wm * 32 + mt * 16 + g;
                af[mt][0] = ldh2(&sA[bf][r    ][kb + 2 * tig]);
                af[mt][1] = ldh2(&sA[bf][r + 8][kb + 2 * tig]);
                af[mt][2] = ldh2(&sA[bf][r    ][kb + 2 * tig + 8]);
                af[mt][3] = ldh2(&sA[bf][r + 8][kb + 2 * tig + 8]);
            }
#pragma unroll
            for (int nt = 0; nt < 8; nt++) {
                const int n = wn * 64 + nt * 8 + g;
                uint32_t b0 = ldh2(&sB[bf][n][kb + 2 * tig]);
                uint32_t b1 = ldh2(&sB[bf][n][kb + 2 * tig + 8]);
                mma_f16(acc[0][nt], af[0], b0, b1);
                mma_f16(acc[1][nt], af[1], b0, b1);
            }
        }
        if (kt < 31) {
            const int nb = (kt + 1) & 1;
#pragma unroll
            for (int i = 0; i < 4; i++) {
                int idx = tid + i * 256, r = idx >> 3, c = (idx & 7) * 4;
                *reinterpret_cast<__half2*>(&sA[nb][r][c])     = __floats2half2_rn(ra[i].x, ra[i].y);
                *reinterpret_cast<__half2*>(&sA[nb][r][c + 2]) = __floats2half2_rn(ra[i].z, ra[i].w);
                *reinterpret_cast<__half2*>(&sB[nb][r][c])     = __floats2half2_rn(rb[i].x, rb[i].y);
                *reinterpret_cast<__half2*>(&sB[nb][r][c + 2]) = __floats2half2_rn(rb[i].z, rb[i].w);
            }
        }
        __syncthreads();
    }

    // epilogue
    if (blockIdx.z < 2) {
        __half* Y = (blockIdx.z == 0) ? g_Qh : g_Kh;
#pragma unroll
        for (int mt = 0; mt < 2; mt++) {
            const int r = m0 + wm * 32 + mt * 16 + g;
#pragma unroll
            for (int nt = 0; nt < 8; nt++) {
                const int c = n0 + wn * 64 + nt * 8 + 2 * tig;
                const float b0 = bias[c], b1 = bias[c + 1];
                *reinterpret_cast<__half2*>(&Y[(size_t)r * HID + c]) =
                    __floats2half2_rn(acc[mt][nt][0] + b0, acc[mt][nt][1] + b1);
                *reinterpret_cast<__half2*>(&Y[(size_t)(r + 8) * HID + c]) =
                    __floats2half2_rn(acc[mt][nt][2] + b0, acc[mt][nt][3] + b1);
            }
        }
    } else {
        // V transposed: g_Vt[(b*NH+h)*HD + hd][s]
#pragma unroll
        for (int mt = 0; mt < 2; mt++) {
            const int r = m0 + wm * 32 + mt * 16 + g;
#pragma unroll
            for (int nt = 0; nt < 8; nt++) {
                const int c = n0 + wn * 64 + nt * 8 + 2 * tig;
                const float b0 = bias[c], b1 = bias[c + 1];
                float v[4] = { acc[mt][nt][0] + b0, acc[mt][nt][1] + b1,
                               acc[mt][nt][2] + b0, acc[mt][nt][3] + b1 };
                int rows[2] = { r, r + 8 };
#pragma unroll
                for (int q = 0; q < 4; q++) {
                    int rr = rows[q >> 1];
                    int cc = c + (q & 1);
                    int bb = rr >> 11, s = rr & 2047;
                    int hh = cc >> 6, hd = cc & 63;
                    g_Vt[((size_t)(bb * NH + hh) * HD + hd) * S_LEN + s] = __float2half(v[q]);
                }
            }
        }
    }
}

// ============================================================================
// Kernel 2: attention, fp16 mma, cp.async double-buffered, register P.
// One CTA per (b, h, 128-row q tile). 8 warps: wm = wid&3 (rows), wn = wid>>2.
// ============================================================================
#define SKW 72    // K tile stride in halves (128 rows x 64 hd)
#define SVW 136   // Vt tile stride in halves (64 hd rows x 128 s)
#define OFF_K0 0
#define OFF_K1 18432
#define OFF_V0 36864
#define OFF_V1 54272
#define OFF_SL 71680
#define ATTN_SMEM 72192

__device__ __forceinline__ void load_k_tile(uint32_t sbase, const __half* Kg,
                                            int k0, int tid) {
#pragma unroll
    for (int j = 0; j < 4; j++) {
        int id = tid + j * 256;        // 1024 chunks of 16B
        int r = id >> 3, ch = id & 7;
        cp16(sbase + (uint32_t)(r * SKW + ch * 8) * 2,
             Kg + (size_t)(k0 + r) * HID + ch * 8);
    }
}
__device__ __forceinline__ void load_v_tile(uint32_t sbase, const __half* Vt,
                                            int k0, int tid) {
#pragma unroll
    for (int j = 0; j < 4; j++) {
        int id = tid + j * 256;        // 1024 chunks of 16B
        int hd = id >> 4, ch = id & 15;
        cp16(sbase + (uint32_t)(hd * SVW + ch * 8) * 2,
             Vt + (size_t)hd * S_LEN + k0 + ch * 8);
    }
}

__global__ __launch_bounds__(256, 1) void attn_kernel(
    float* __restrict__ ctx_out, float* __restrict__ probs_out)
{
    extern __shared__ char sm[];
    const uint32_t smb = (uint32_t)__cvta_generic_to_shared(sm);
    const int tid = threadIdx.x, wid = tid >> 5, lane = tid & 31;
    const int g = lane >> 2, tig = lane & 3;
    const int wm = wid & 3, wn = wid >> 2;
    const int q0 = blockIdx.x * 128, h = blockIdx.y, b = blockIdx.z;

    const __half* Qg = g_Qh + (size_t)b * S_LEN * HID + (size_t)h * HD;
    const __half* Kg = g_Kh + (size_t)b * S_LEN * HID + (size_t)h * HD;
    const __half* Vt = g_Vt + (size_t)(b * NH + h) * HD * S_LEN;
    float* sL = reinterpret_cast<float*>(sm + OFF_SL);

    // Q fragments: register-resident for the whole kernel
    uint32_t qf[4][2][4];
#pragma unroll
    for (int ks = 0; ks < 4; ks++)
#pragma unroll
        for (int mt = 0; mt < 2; mt++) {
            const __half* qp = Qg + (size_t)(q0 + wm * 32 + mt * 16 + g) * HID
                               + ks * 16 + 2 * tig;
            qf[ks][mt][0] = ldh2(qp);
            qf[ks][mt][1] = ldh2(qp + 8 * HID);
            qf[ks][mt][2] = ldh2(qp + 8);
            qf[ks][mt][3] = ldh2(qp + 8 * HID + 8);
        }

    if (tid < 128) sL[tid] = 0.f;
    __syncthreads();

    // ---------------- sweep 1: denominators ----------------
    load_k_tile(smb + OFF_K0, Kg, 0, tid);
    cp_commit();
    float rs[4] = {0.f, 0.f, 0.f, 0.f};

    for (int kt = 0; kt < 16; kt++) {
        if (kt < 15) {
            load_k_tile(smb + ((kt + 1) & 1 ? OFF_K1 : OFF_K0), Kg, (kt + 1) * 128, tid);
            cp_commit();
            asm volatile("cp.async.wait_group 1;");
        } else {
            asm volatile("cp.async.wait_group 0;");
        }
        __syncthreads();

        const __half* sK = reinterpret_cast<const __half*>(sm + ((kt & 1) ? OFF_K1 : OFF_K0));
        float accS[2][8][4];
#pragma unroll
        for (int i = 0; i < 2; i++)
#pragma unroll
            for (int j = 0; j < 8; j++)
#pragma unroll
                for (int k = 0; k < 4; k++) accS[i][j][k] = 0.f;
#pragma unroll
        for (int ks = 0; ks < 4; ks++)
#pragma unroll
            for (int nt = 0; nt < 8; nt++) {
                const __half* bp = sK + (wn * 64 + nt * 8 + g) * SKW + ks * 16 + 2 * tig;
                uint32_t b0 = ldh2(bp), b1 = ldh2(bp + 8);
                mma_f16(accS[0][nt], qf[ks][0], b0, b1);
                mma_f16(accS[1][nt], qf[ks][1], b0, b1);
            }
#pragma unroll
        for (int mt = 0; mt < 2; mt++)
#pragma unroll
            for (int nt = 0; nt < 8; nt++) {
                rs[mt * 2]     += __expf(accS[mt][nt][0] * 0.125f) + __expf(accS[mt][nt][1] * 0.125f);
                rs[mt * 2 + 1] += __expf(accS[mt][nt][2] * 0.125f) + __expf(accS[mt][nt][3] * 0.125f);
            }
        __syncthreads();
    }
#pragma unroll
    for (int o = 1; o < 4; o <<= 1)
#pragma unroll
        for (int j = 0; j < 4; j++) rs[j] += __shfl_xor_sync(0xffffffffu, rs[j], o);
    if (tig == 0) {
        atomicAdd(&sL[wm * 32      + g], rs[0]);
        atomicAdd(&sL[wm * 32 + 8  + g], rs[1]);
        atomicAdd(&sL[wm * 32 + 16 + g], rs[2]);
        atomicAdd(&sL[wm * 32 + 24 + g], rs[3]);
    }
    __syncthreads();
    float rinv[4];
#pragma unroll
    for (int j = 0; j < 4; j++) rinv[j] = 1.0f / sL[wm * 32 + j * 8 + g];
    __syncthreads();

    // ---------------- sweep 2: probs + ctx ----------------
    load_k_tile(smb + OFF_K0, Kg, 0, tid);
    load_v_tile(smb + OFF_V0, Vt, 0, tid);
    cp_commit();

    float accO[2][8][4];
#pragma unroll
    for (int i = 0; i < 2; i++)
#pragma unroll
        for (int j = 0; j < 8; j++)
#pragma unroll
            for (int k = 0; k < 4; k++) accO[i][j][k] = 0.f;

    const size_t pb = ((size_t)(b * NH + h) * S_LEN + q0) * S_LEN;

    for (int kt = 0; kt < 16; kt++) {
        if (kt < 15) {
            load_k_tile(smb + ((kt + 1) & 1 ? OFF_K1 : OFF_K0), Kg, (kt + 1) * 128, tid);
            load_v_tile(smb + ((kt + 1) & 1 ? OFF_V1 : OFF_V0), Vt, (kt + 1) * 128, tid);
            cp_commit();
            asm volatile("cp.async.wait_group 1;");
        } else {
            asm volatile("cp.async.wait_group 0;");
        }
        __syncthreads();

        const __half* sK  = reinterpret_cast<const __half*>(sm + ((kt & 1) ? OFF_K1 : OFF_K0));
        const __half* sVt = reinterpret_cast<const __half*>(sm + ((kt & 1) ? OFF_V1 : OFF_V0));

        float accS[2][8][4];
#pragma unroll
        for (int i = 0; i < 2; i++)
#pragma unroll
            for (int j = 0; j < 8; j++)
#pragma unroll
                for (int k = 0; k < 4; k++) accS[i][j][k] = 0.f;
#pragma unroll
        for (int ks = 0; ks < 4; ks++)
#pragma unroll
            for (int nt = 0; nt < 8; nt++) {
                const __half* bp = sK + (wn * 64 + nt * 8 + g) * SKW + ks * 16 + 2 * tig;
                uint32_t b0 = ldh2(bp), b1 = ldh2(bp + 8);
                mma_f16(accS[0][nt], qf[ks][0], b0, b1);
                mma_f16(accS[1][nt], qf[ks][1], b0, b1);
            }

        // exp + normalize, write probs, keep p in accS
#pragma unroll
        for (int mt = 0; mt < 2; mt++) {
            const int r0 = wm * 32 + mt * 16 + g;
#pragma unroll
            for (int nt = 0; nt < 8; nt++) {
                float p0 = __expf(accS[mt][nt][0] * 0.125f) * rinv[mt * 2];
                float p1 = __expf(accS[mt][nt][1] * 0.125f) * rinv[mt * 2];
                float p2 = __expf(accS[mt][nt][2] * 0.125f) * rinv[mt * 2 + 1];
                float p3 = __expf(accS[mt][nt][3] * 0.125f) * rinv[mt * 2 + 1];
                accS[mt][nt][0] = p0; accS[mt][nt][1] = p1;
                accS[mt][nt][2] = p2; accS[mt][nt][3] = p3;
                const size_t cidx = (size_t)kt * 128 + wn * 64 + nt * 8 + 2 * tig;
                *reinterpret_cast<float2*>(probs_out + pb + (size_t)r0 * S_LEN + cidx) =
                    make_float2(p0, p1);
                *reinterpret_cast<float2*>(probs_out + pb + (size_t)(r0 + 8) * S_LEN + cidx) =
                    make_float2(p2, p3);
            }
        }

        // pack P into fp16 A-fragments (register-only)
        uint32_t ph[2][4][4];
#pragma unroll
        for (int mt = 0; mt < 2; mt++)
#pragma unroll
            for (int j = 0; j < 4; j++) {
                ph[mt][j][0] = pack2(accS[mt][2 * j][0],     accS[mt][2 * j][1]);
                ph[mt][j][1] = pack2(accS[mt][2 * j][2],     accS[mt][2 * j][3]);
                ph[mt][j][2] = pack2(accS[mt][2 * j + 1][0], accS[mt][2 * j + 1][1]);
                ph[mt][j][3] = pack2(accS[mt][2 * j + 1][2], accS[mt][2 * j + 1][3]);
            }

        // O += P * V  (this warp's 64-k slice; partial over wn)
#pragma unroll
        for (int j = 0; j < 4; j++)
#pragma unroll
            for (int nt = 0; nt < 8; nt++) {
                const __half* vp = sVt + (nt * 8 + g) * SVW + wn * 64 + j * 16 + 2 * tig;
                uint32_t b0 = ldh2(vp), b1 = ldh2(vp + 8);
                mma_f16(accO[0][nt], ph[0][j], b0, b1);
                mma_f16(accO[1][nt], ph[1][j], b0, b1);
            }
        __syncthreads();
    }

    // ---------------- O reduction across wn halves + ctx write ----------------
    float* sRed = reinterpret_cast<float*>(sm);   // [128][68], overlaps K bufs (done)
    if (wn == 0) {
#pragma unroll
        for (int mt = 0; mt < 2; mt++) {
            const int r = wm * 32 + mt * 16 + g;
#pragma unroll
            for (int nt = 0; nt < 8; nt++) {
                const int c = nt * 8 + 2 * tig;
                *reinterpret_cast<float2*>(&sRed[r * 68 + c]) =
                    make_float2(accO[mt][nt][0], accO[mt][nt][1]);
                *reinterpret_cast<float2*>(&sRed[(r + 8) * 68 + c]) =
                    make_float2(accO[mt][nt][2], accO[mt][nt][3]);
            }
        }
    }
    __syncthreads();
    if (wn == 1) {
#pragma unroll
        for (int mt = 0; mt < 2; mt++) {
            const int r = wm * 32 + mt * 16 + g;
#pragma unroll
            for (int nt = 0; nt < 8; nt++) {
                const int c = nt * 8 + 2 * tig;
                float2 a = *reinterpret_cast<float2*>(&sRed[r * 68 + c]);
                *reinterpret_cast<float2*>(&sRed[r * 68 + c]) =
                    make_float2(a.x + accO[mt][nt][0], a.y + accO[mt][nt][1]);
                float2 d = *reinterpret_cast<float2*>(&sRed[(r + 8) * 68 + c]);
                *reinterpret_cast<float2*>(&sRed[(r + 8) * 68 + c]) =
                    make_float2(d.x + accO[mt][nt][2], d.y + accO[mt][nt][3]);
            }
        }
    }
    __syncthreads();
    {
        const int row = tid >> 1, cb = (tid & 1) * 32;
        float* cw = ctx_out + (size_t)(b * S_LEN + q0 + row) * HID + h * HD + cb;
        const float* rr = sRed + row * 68 + cb;
#pragma unroll
        for (int i = 0; i < 8; i++)
            *reinterpret_cast<float4*>(cw + 4 * i) =
                *reinterpret_cast<const float4*>(rr + 4 * i);
    }
}

// ============================================================================
// launch
// ============================================================================
extern "C" void kernel_launch(void* const* d_in, const int* in_sizes, int n_in,
                              void* d_out, int out_size)
{
    const float* X  = (const float*)d_in[0];
    const float* Wq = (const float*)d_in[1];
    const float* bq = (const float*)d_in[2];
    const float* Wk = (const float*)d_in[3];
    const float* bk = (const float*)d_in[4];
    const float* Wv = (const float*)d_in[5];
    const float* bv = (const float*)d_in[6];

    float* ctx   = (float*)d_out;                         // [2,2048,1024]
    float* probs = ctx + (size_t)BATCH * S_LEN * HID;     // [2,16,2048,2048]

    qkv_kernel<<<dim3(HID / 128, M_TOT / 128, 3), 256>>>(X, Wq, bq, Wk, bk, Wv, bv);

    cudaFuncSetAttribute(attn_kernel, cudaFuncAttributeMaxDynamicSharedMemorySize,
                         ATTN_SMEM);
    attn_kernel<<<dim3(S_LEN / 128, NH, BATCH), 256, ATTN_SMEM>>>(ctx, probs);
}

// round 8
// speedup vs baseline: 2.2575x; 1.0673x over previous
#include <cuda_runtime.h>
#include <cuda_fp16.h>
#include <cstdint>
#include <cstddef>

#define S_LEN 2048
#define HID   1024
#define NH    16
#define HD    64
#define BATCH 2
#define M_TOT (BATCH * S_LEN)   // 4096

// ---------------- scratch (static device arrays; no allocation) -------------
__device__ __half g_Xh[(size_t)M_TOT * HID];
__device__ __half g_Wh[3ull * HID * HID];
__device__ __half g_Qh[(size_t)M_TOT * HID];
__device__ __half g_Kh[(size_t)M_TOT * HID];
__device__ __half g_Vt[(size_t)BATCH * NH * HD * S_LEN];  // [(b*NH+h)*HD+hd][s]

// ---------------- helpers ---------------------------------------------------
__device__ __forceinline__ void mma_f16(float d[4], const uint32_t a[4],
                                        uint32_t b0, uint32_t b1) {
    asm volatile(
        "mma.sync.aligned.m16n8k16.row.col.f32.f16.f16.f32 "
        "{%0,%1,%2,%3}, {%4,%5,%6,%7}, {%8,%9}, {%0,%1,%2,%3};\n"
        : "+f"(d[0]), "+f"(d[1]), "+f"(d[2]), "+f"(d[3])
        : "r"(a[0]), "r"(a[1]), "r"(a[2]), "r"(a[3]), "r"(b0), "r"(b1));
}
__device__ __forceinline__ uint32_t pack2(float lo, float hi) {
    __half2 h = __floats2half2_rn(lo, hi);
    return *reinterpret_cast<uint32_t*>(&h);
}
__device__ __forceinline__ uint32_t ldh2(const __half* p) {
    return *reinterpret_cast<const uint32_t*>(p);
}
__device__ __forceinline__ void cp16(uint32_t dst, const void* src) {
    asm volatile("cp.async.cg.shared.global [%0], [%1], 16;" :: "r"(dst), "l"(src));
}
__device__ __forceinline__ void cp_commit() {
    asm volatile("cp.async.commit_group;");
}
__device__ __forceinline__ void cp_wait1() { asm volatile("cp.async.wait_group 1;"); }
__device__ __forceinline__ void cp_wait0() { asm volatile("cp.async.wait_group 0;"); }

// ============================================================================
// Kernel 0: fp32 -> fp16 conversion of X, Wq, Wk, Wv
// ============================================================================
#define NX4 ((size_t)M_TOT * HID / 4)        // 1048576
#define NW4 ((size_t)HID * HID / 4)          // 262144
#define NCVT (NX4 + 3 * NW4)

__global__ __launch_bounds__(256) void cvt_kernel(
    const float* __restrict__ X, const float* __restrict__ Wq,
    const float* __restrict__ Wk, const float* __restrict__ Wv)
{
    size_t i = (size_t)blockIdx.x * blockDim.x + threadIdx.x;
    if (i >= NCVT) return;
    const float* src; __half* dst; size_t j;
    if (i < NX4)                { src = X;  dst = g_Xh;            j = i; }
    else if (i < NX4 + NW4)     { src = Wq; dst = g_Wh;            j = i - NX4; }
    else if (i < NX4 + 2 * NW4) { src = Wk; dst = g_Wh + NW4 * 4;  j = i - NX4 - NW4; }
    else                        { src = Wv; dst = g_Wh + NW4 * 8;  j = i - NX4 - 2 * NW4; }
    float4 v = *reinterpret_cast<const float4*>(src + 4 * j);
    __half2 h0 = __floats2half2_rn(v.x, v.y);
    __half2 h1 = __floats2half2_rn(v.z, v.w);
    uint2 out = { *reinterpret_cast<uint32_t*>(&h0), *reinterpret_cast<uint32_t*>(&h1) };
    *reinterpret_cast<uint2*>(dst + 4 * j) = out;
}

// ============================================================================
// Kernel 1: QKV projection.  fp16 cp.async GEMM, CTA 128x128, BK=64,
// 3-stage single-sync pipeline. z selects Q/K/Vt output.
// ============================================================================
#define QSTR 72                               // smem row stride in halves
#define QSZ  (128 * QSTR * 2)                 // 18432 B per tile
#define QSA(i) ((i) * QSZ)
#define QSB(i) (3 * QSZ + (i) * QSZ)
#define QKV_SMEM (6 * QSZ)                    // 110592 B

__device__ __forceinline__ void qkv_load(uint32_t sbase, const __half* g,
                                         int row0, int kt, int tid) {
#pragma unroll
    for (int j = 0; j < 4; j++) {
        int id = tid + j * 256;               // 1024 chunks of 16B
        int r = id >> 3, ch = id & 7;
        cp16(sbase + (uint32_t)(r * QSTR + ch * 8) * 2,
             g + (size_t)(row0 + r) * HID + kt * 64 + ch * 8);
    }
}

__global__ __launch_bounds__(256, 1) void qkv_kernel(
    const float* __restrict__ bq, const float* __restrict__ bk,
    const float* __restrict__ bv)
{
    extern __shared__ char smq[];
    const uint32_t smb = (uint32_t)__cvta_generic_to_shared(smq);
    const int z = blockIdx.z;
    const __half* A = g_Xh;
    const __half* Bm = g_Wh + (size_t)z * HID * HID;
    const float* bias = (z == 0) ? bq : (z == 1) ? bk : bv;

    const int tid = threadIdx.x, wid = tid >> 5, lane = tid & 31;
    const int g = lane >> 2, tig = lane & 3;
    const int wm = wid & 3, wn = wid >> 2;
    const int m0 = blockIdx.y * 128, n0 = blockIdx.x * 128;

    float acc[2][8][4];
#pragma unroll
    for (int i = 0; i < 2; i++)
#pragma unroll
        for (int j = 0; j < 8; j++)
#pragma unroll
            for (int k = 0; k < 4; k++) acc[i][j][k] = 0.f;

    qkv_load(smb + QSA(0), A, m0, 0, tid);
    qkv_load(smb + QSB(0), Bm, n0, 0, tid);
    cp_commit();
    qkv_load(smb + QSA(1), A, m0, 1, tid);
    qkv_load(smb + QSB(1), Bm, n0, 1, tid);
    cp_commit();

    for (int kt = 0; kt < 16; kt++) {
        if (kt < 15) cp_wait1(); else cp_wait0();
        __syncthreads();
        if (kt + 2 < 16) {
            const int s = (kt + 2) % 3;
            qkv_load(smb + QSA(s), A, m0, kt + 2, tid);
            qkv_load(smb + QSB(s), Bm, n0, kt + 2, tid);
            cp_commit();
        }
        const __half* sA = reinterpret_cast<const __half*>(smq + QSA(kt % 3));
        const __half* sB = reinterpret_cast<const __half*>(smq + QSB(kt % 3));
#pragma unroll
        for (int ks = 0; ks < 4; ks++) {
            const int kb = ks * 16;
            uint32_t af[2][4];
#pragma unroll
            for (int mt = 0; mt < 2; mt++) {
                const __half* ap = sA + (wm * 32 + mt * 16 + g) * QSTR + kb + 2 * tig;
                af[mt][0] = ldh2(ap);
                af[mt][1] = ldh2(ap + 8 * QSTR);
                af[mt][2] = ldh2(ap + 8);
                af[mt][3] = ldh2(ap + 8 * QSTR + 8);
            }
#pragma unroll
            for (int nt = 0; nt < 8; nt++) {
                const __half* bp = sB + (wn * 64 + nt * 8 + g) * QSTR + kb + 2 * tig;
                uint32_t b0 = ldh2(bp), b1 = ldh2(bp + 8);
                mma_f16(acc[0][nt], af[0], b0, b1);
                mma_f16(acc[1][nt], af[1], b0, b1);
            }
        }
    }
    __syncthreads();

    if (z < 2) {
        __half* Y = (z == 0) ? g_Qh : g_Kh;
#pragma unroll
        for (int mt = 0; mt < 2; mt++) {
            const int r = m0 + wm * 32 + mt * 16 + g;
#pragma unroll
            for (int nt = 0; nt < 8; nt++) {
                const int c = n0 + wn * 64 + nt * 8 + 2 * tig;
                const float b0 = bias[c], b1 = bias[c + 1];
                *reinterpret_cast<__half2*>(&Y[(size_t)r * HID + c]) =
                    __floats2half2_rn(acc[mt][nt][0] + b0, acc[mt][nt][1] + b1);
                *reinterpret_cast<__half2*>(&Y[(size_t)(r + 8) * HID + c]) =
                    __floats2half2_rn(acc[mt][nt][2] + b0, acc[mt][nt][3] + b1);
            }
        }
    } else {
        // V: transpose through SMEM, then coalesced stores to g_Vt[(b,h,hd)][s]
        __half* sT = reinterpret_cast<__half*>(smq);   // [128 cols][136] stride
#pragma unroll
        for (int mt = 0; mt < 2; mt++) {
            const int rl = wm * 32 + mt * 16 + g;
#pragma unroll
            for (int nt = 0; nt < 8; nt++) {
                const int cl = wn * 64 + nt * 8 + 2 * tig;
                const float b0 = bias[n0 + cl], b1 = bias[n0 + cl + 1];
                sT[cl * 136 + rl]             = __float2half(acc[mt][nt][0] + b0);
                sT[(cl + 1) * 136 + rl]       = __float2half(acc[mt][nt][1] + b1);
                sT[cl * 136 + rl + 8]         = __float2half(acc[mt][nt][2] + b0);
                sT[(cl + 1) * 136 + rl + 8]   = __float2half(acc[mt][nt][3] + b1);
            }
        }
        __syncthreads();
        const int bb = m0 >> 11;          // batch of this row tile
        const int s0 = m0 & 2047;
#pragma unroll
        for (int j = 0; j < 8; j++) {
            int id = tid + j * 256;       // 2048 chunks of 16B
            int cl = id >> 4, ch = id & 15;
            int c = n0 + cl;
            int hh = c >> 6, hd = c & 63;
            *reinterpret_cast<uint4*>(
                g_Vt + ((size_t)(bb * NH + hh) * HD + hd) * S_LEN + s0 + ch * 8) =
                *reinterpret_cast<const uint4*>(sT + cl * 136 + ch * 8);
        }
    }
}

// ============================================================================
// Kernel 2: attention.  fp16 mma, 3-stage cp.async, single sync per tile.
// One CTA per (b, h, 128-row q tile). 8 warps: wm = wid&3, wn = wid>>2.
// ============================================================================
#define SKW 72    // K tile stride (halves): 128 rows x 64 hd
#define SVW 136   // Vt tile stride (halves): 64 hd rows x 128 s
#define SZK (128 * SKW * 2)     // 18432
#define SZV (64 * SVW * 2)      // 17408
#define OFF_KB(i) ((i) * SZK)
#define OFF_VB(i) (3 * SZK + (i) * SZV)
#define OFF_SL    (3 * SZK + 3 * SZV)
#define ATTN_SMEM (OFF_SL + 512)    // 108032

__device__ __forceinline__ void load_k_tile(uint32_t sbase, const __half* Kg,
                                            int k0, int tid) {
#pragma unroll
    for (int j = 0; j < 4; j++) {
        int id = tid + j * 256;
        int r = id >> 3, ch = id & 7;
        cp16(sbase + (uint32_t)(r * SKW + ch * 8) * 2,
             Kg + (size_t)(k0 + r) * HID + ch * 8);
    }
}
__device__ __forceinline__ void load_v_tile(uint32_t sbase, const __half* Vt,
                                            int k0, int tid) {
#pragma unroll
    for (int j = 0; j < 4; j++) {
        int id = tid + j * 256;
        int hd = id >> 4, ch = id & 15;
        cp16(sbase + (uint32_t)(hd * SVW + ch * 8) * 2,
             Vt + (size_t)hd * S_LEN + k0 + ch * 8);
    }
}

__global__ __launch_bounds__(256, 1) void attn_kernel(
    float* __restrict__ ctx_out, float* __restrict__ probs_out)
{
    extern __shared__ char sm[];
    const uint32_t smb = (uint32_t)__cvta_generic_to_shared(sm);
    const int tid = threadIdx.x, wid = tid >> 5, lane = tid & 31;
    const int g = lane >> 2, tig = lane & 3;
    const int wm = wid & 3, wn = wid >> 2;
    const int q0 = blockIdx.x * 128, h = blockIdx.y, b = blockIdx.z;

    const __half* Qg = g_Qh + (size_t)b * S_LEN * HID + (size_t)h * HD;
    const __half* Kg = g_Kh + (size_t)b * S_LEN * HID + (size_t)h * HD;
    const __half* Vt = g_Vt + (size_t)(b * NH + h) * HD * S_LEN;
    float* sL = reinterpret_cast<float*>(sm + OFF_SL);

    // Q fragments: register-resident for the whole kernel
    uint32_t qf[4][2][4];
#pragma unroll
    for (int ks = 0; ks < 4; ks++)
#pragma unroll
        for (int mt = 0; mt < 2; mt++) {
            const __half* qp = Qg + (size_t)(q0 + wm * 32 + mt * 16 + g) * HID
                               + ks * 16 + 2 * tig;
            qf[ks][mt][0] = ldh2(qp);
            qf[ks][mt][1] = ldh2(qp + 8 * HID);
            qf[ks][mt][2] = ldh2(qp + 8);
            qf[ks][mt][3] = ldh2(qp + 8 * HID + 8);
        }

    if (tid < 128) sL[tid] = 0.f;
    __syncthreads();

    // ---------------- sweep 1: denominators ----------------
    load_k_tile(smb + OFF_KB(0), Kg, 0, tid); cp_commit();
    load_k_tile(smb + OFF_KB(1), Kg, 128, tid); cp_commit();
    float rs[4] = {0.f, 0.f, 0.f, 0.f};

    for (int kt = 0; kt < 16; kt++) {
        if (kt < 15) cp_wait1(); else cp_wait0();
        __syncthreads();
        if (kt + 2 < 16) {
            load_k_tile(smb + OFF_KB((kt + 2) % 3), Kg, (kt + 2) * 128, tid);
            cp_commit();
        }
        const __half* sK = reinterpret_cast<const __half*>(sm + OFF_KB(kt % 3));
        float accS[2][8][4];
#pragma unroll
        for (int i = 0; i < 2; i++)
#pragma unroll
            for (int j = 0; j < 8; j++)
#pragma unroll
                for (int k = 0; k < 4; k++) accS[i][j][k] = 0.f;
#pragma unroll
        for (int ks = 0; ks < 4; ks++)
#pragma unroll
            for (int nt = 0; nt < 8; nt++) {
                const __half* bp = sK + (wn * 64 + nt * 8 + g) * SKW + ks * 16 + 2 * tig;
                uint32_t b0 = ldh2(bp), b1 = ldh2(bp + 8);
                mma_f16(accS[0][nt], qf[ks][0], b0, b1);
                mma_f16(accS[1][nt], qf[ks][1], b0, b1);
            }
#pragma unroll
        for (int mt = 0; mt < 2; mt++)
#pragma unroll
            for (int nt = 0; nt < 8; nt++) {
                rs[mt * 2]     += __expf(accS[mt][nt][0] * 0.125f) + __expf(accS[mt][nt][1] * 0.125f);
                rs[mt * 2 + 1] += __expf(accS[mt][nt][2] * 0.125f) + __expf(accS[mt][nt][3] * 0.125f);
            }
    }
#pragma unroll
    for (int o = 1; o < 4; o <<= 1)
#pragma unroll
        for (int j = 0; j < 4; j++) rs[j] += __shfl_xor_sync(0xffffffffu, rs[j], o);
    __syncthreads();          // all warps done with K buffers + sL zeroed visible
    if (tig == 0) {
        atomicAdd(&sL[wm * 32      + g], rs[0]);
        atomicAdd(&sL[wm * 32 + 8  + g], rs[1]);
        atomicAdd(&sL[wm * 32 + 16 + g], rs[2]);
        atomicAdd(&sL[wm * 32 + 24 + g], rs[3]);
    }
    __syncthreads();
    float rinv[4];
#pragma unroll
    for (int j = 0; j < 4; j++) rinv[j] = 1.0f / sL[wm * 32 + j * 8 + g];
    __syncthreads();

    // ---------------- sweep 2: probs + ctx ----------------
    load_k_tile(smb + OFF_KB(0), Kg, 0, tid);
    load_v_tile(smb + OFF_VB(0), Vt, 0, tid);
    cp_commit();
    load_k_tile(smb + OFF_KB(1), Kg, 128, tid);
    load_v_tile(smb + OFF_VB(1), Vt, 128, tid);
    cp_commit();

    float accO[2][8][4];
#pragma unroll
    for (int i = 0; i < 2; i++)
#pragma unroll
        for (int j = 0; j < 8; j++)
#pragma unroll
            for (int k = 0; k < 4; k++) accO[i][j][k] = 0.f;

    const size_t pb = ((size_t)(b * NH + h) * S_LEN + q0) * S_LEN;

    for (int kt = 0; kt < 16; kt++) {
        if (kt < 15) cp_wait1(); else cp_wait0();
        __syncthreads();
        if (kt + 2 < 16) {
            load_k_tile(smb + OFF_KB((kt + 2) % 3), Kg, (kt + 2) * 128, tid);
            load_v_tile(smb + OFF_VB((kt + 2) % 3), Vt, (kt + 2) * 128, tid);
            cp_commit();
        }
        const __half* sK  = reinterpret_cast<const __half*>(sm + OFF_KB(kt % 3));
        const __half* sVt = reinterpret_cast<const __half*>(sm + OFF_VB(kt % 3));

        float accS[2][8][4];
#pragma unroll
        for (int i = 0; i < 2; i++)
#pragma unroll
            for (int j = 0; j < 8; j++)
#pragma unroll
                for (int k = 0; k < 4; k++) accS[i][j][k] = 0.f;
#pragma unroll
        for (int ks = 0; ks < 4; ks++)
#pragma unroll
            for (int nt = 0; nt < 8; nt++) {
                const __half* bp = sK + (wn * 64 + nt * 8 + g) * SKW + ks * 16 + 2 * tig;
                uint32_t b0 = ldh2(bp), b1 = ldh2(bp + 8);
                mma_f16(accS[0][nt], qf[ks][0], b0, b1);
                mma_f16(accS[1][nt], qf[ks][1], b0, b1);
            }

        // exp + normalize, write probs, keep p in accS
#pragma unroll
        for (int mt = 0; mt < 2; mt++) {
            const int r0 = wm * 32 + mt * 16 + g;
#pragma unroll
            for (int nt = 0; nt < 8; nt++) {
                float p0 = __expf(accS[mt][nt][0] * 0.125f) * rinv[mt * 2];
                float p1 = __expf(accS[mt][nt][1] * 0.125f) * rinv[mt * 2];
                float p2 = __expf(accS[mt][nt][2] * 0.125f) * rinv[mt * 2 + 1];
                float p3 = __expf(accS[mt][nt][3] * 0.125f) * rinv[mt * 2 + 1];
                accS[mt][nt][0] = p0; accS[mt][nt][1] = p1;
                accS[mt][nt][2] = p2; accS[mt][nt][3] = p3;
                const size_t cidx = (size_t)kt * 128 + wn * 64 + nt * 8 + 2 * tig;
                *reinterpret_cast<float2*>(probs_out + pb + (size_t)r0 * S_LEN + cidx) =
                    make_float2(p0, p1);
                *reinterpret_cast<float2*>(probs_out + pb + (size_t)(r0 + 8) * S_LEN + cidx) =
                    make_float2(p2, p3);
            }
        }

        // pack P into fp16 A-fragments (register-only)
        uint32_t ph[2][4][4];
#pragma unroll
        for (int mt = 0; mt < 2; mt++)
#pragma unroll
            for (int j = 0; j < 4; j++) {
                ph[mt][j][0] = pack2(accS[mt][2 * j][0],     accS[mt][2 * j][1]);
                ph[mt][j][1] = pack2(accS[mt][2 * j][2],     accS[mt][2 * j][3]);
                ph[mt][j][2] = pack2(accS[mt][2 * j + 1][0], accS[mt][2 * j + 1][1]);
                ph[mt][j][3] = pack2(accS[mt][2 * j + 1][2], accS[mt][2 * j + 1][3]);
            }

        // O += P * V  (this warp's 64-k slice; partial over wn)
#pragma unroll
        for (int j = 0; j < 4; j++)
#pragma unroll
            for (int nt = 0; nt < 8; nt++) {
                const __half* vp = sVt + (nt * 8 + g) * SVW + wn * 64 + j * 16 + 2 * tig;
                uint32_t b0 = ldh2(vp), b1 = ldh2(vp + 8);
                mma_f16(accO[0][nt], ph[0][j], b0, b1);
                mma_f16(accO[1][nt], ph[1][j], b0, b1);
            }
    }
    __syncthreads();   // K/V buffers dead; reuse base of smem for O reduction

    // ---------------- O reduction across wn halves + ctx write ----------------
    float* sRed = reinterpret_cast<float*>(sm);   // [128][68]
    if (wn == 0) {
#pragma unroll
        for (int mt = 0; mt < 2; mt++) {
            const int r = wm * 32 + mt * 16 + g;
#pragma unroll
            for (int nt = 0; nt < 8; nt++) {
                const int c = nt * 8 + 2 * tig;
                *reinterpret_cast<float2*>(&sRed[r * 68 + c]) =
                    make_float2(accO[mt][nt][0], accO[mt][nt][1]);
                *reinterpret_cast<float2*>(&sRed[(r + 8) * 68 + c]) =
                    make_float2(accO[mt][nt][2], accO[mt][nt][3]);
            }
        }
    }
    __syncthreads();
    if (wn == 1) {
#pragma unroll
        for (int mt = 0; mt < 2; mt++) {
            const int r = wm * 32 + mt * 16 + g;
#pragma unroll
            for (int nt = 0; nt < 8; nt++) {
                const int c = nt * 8 + 2 * tig;
                float2 a = *reinterpret_cast<float2*>(&sRed[r * 68 + c]);
                *reinterpret_cast<float2*>(&sRed[r * 68 + c]) =
                    make_float2(a.x + accO[mt][nt][0], a.y + accO[mt][nt][1]);
                float2 d = *reinterpret_cast<float2*>(&sRed[(r + 8) * 68 + c]);
                *reinterpret_cast<float2*>(&sRed[(r + 8) * 68 + c]) =
                    make_float2(d.x + accO[mt][nt][2], d.y + accO[mt][nt][3]);
            }
        }
    }
    __syncthreads();
    {
        const int row = tid >> 1, cb = (tid & 1) * 32;
        float* cw = ctx_out + (size_t)(b * S_LEN + q0 + row) * HID + h * HD + cb;
        const float* rr = sRed + row * 68 + cb;
#pragma unroll
        for (int i = 0; i < 8; i++)
            *reinterpret_cast<float4*>(cw + 4 * i) =
                *reinterpret_cast<const float4*>(rr + 4 * i);
    }
}

// ============================================================================
// launch
// ============================================================================
extern "C" void kernel_launch(void* const* d_in, const int* in_sizes, int n_in,
                              void* d_out, int out_size)
{
    const float* X  = (const float*)d_in[0];
    const float* Wq = (const float*)d_in[1];
    const float* bq = (const float*)d_in[2];
    const float* Wk = (const float*)d_in[3];
    const float* bk = (const float*)d_in[4];
    const float* Wv = (const float*)d_in[5];
    const float* bv = (const float*)d_in[6];

    float* ctx   = (float*)d_out;                         // [2,2048,1024]
    float* probs = ctx + (size_t)BATCH * S_LEN * HID;     // [2,16,2048,2048]

    cvt_kernel<<<(unsigned)((NCVT + 255) / 256), 256>>>(X, Wq, Wk, Wv);

    cudaFuncSetAttribute(qkv_kernel, cudaFuncAttributeMaxDynamicSharedMemorySize,
                         QKV_SMEM);
    qkv_kernel<<<dim3(HID / 128, M_TOT / 128, 3), 256, QKV_SMEM>>>(bq, bk, bv);

    cudaFuncSetAttribute(attn_kernel, cudaFuncAttributeMaxDynamicSharedMemorySize,
                         ATTN_SMEM);
    attn_kernel<<<dim3(S_LEN / 128, NH, BATCH), 256, ATTN_SMEM>>>(ctx, probs);
}